// round 6
// baseline (speedup 1.0000x reference)
#include <cuda_runtime.h>
#include <cmath>

#define HID  640
#define ADIM 128
#define WPB  148     // warp-partials per batch in pass1 -> 2368 warps = 296 blocks
#define MAXB 16

// ---- device scratch (no allocations allowed) ----
__device__ float g_q[MAXB * ADIM];                  // q[b] = Wq @ pos[b]
__device__ float g_r[MAXB * HID];                   // r[b] = scale * Wk^T q[b]
__device__ float g_pacc[(size_t)MAXB * WPB * HID];  // per-warp partial weighted sums
__device__ float g_pm[MAXB * WPB];                  // per-warp running max
__device__ float g_ps[MAXB * WPB];                  // per-warp sum of exp
__device__ float g_wsm[MAXB * WPB];                 // softmax rescale weights
__device__ float g_invS[MAXB];                      // 1 / total denominator
__device__ float g_pooled[MAXB * HID];              // normalized pooled hidden
__device__ float g_y[MAXB * HID];                   // Wv @ pooled (pre-LN)

// ---------------------------------------------------------------------------
// Kernel 1a: q[b,a] = dot(Wq[a,:], pos[b,:])   — one warp per output
// ---------------------------------------------------------------------------
__global__ void __launch_bounds__(256) k_q(const float* __restrict__ pos,
                                           const float* __restrict__ Wq) {
    int gw   = blockIdx.x * 8 + (threadIdx.x >> 5);   // 0..2047
    int lane = threadIdx.x & 31;
    int b = gw >> 7;
    int a = gw & 127;

    const float* wr = Wq + (size_t)a * HID;
    const float* pr = pos + (size_t)b * HID;
    float s = 0.f;
    #pragma unroll
    for (int k = 0; k < HID / 32; k++) {
        int h = lane + 32 * k;
        s += wr[h] * pr[h];
    }
    #pragma unroll
    for (int o = 16; o > 0; o >>= 1) s += __shfl_xor_sync(0xffffffffu, s, o);
    if (lane == 0) g_q[b * ADIM + a] = s;
}

// ---------------------------------------------------------------------------
// Kernel 1b: r[b,h] = scale * sum_a Wk[a,h] * q[b,a]
// ---------------------------------------------------------------------------
__global__ void __launch_bounds__(160) k_r(const float* __restrict__ Wk,
                                           float scale) {
    int b = blockIdx.x;
    int h = blockIdx.y * 160 + threadIdx.x;

    __shared__ float qs[ADIM];
    if (threadIdx.x < ADIM) qs[threadIdx.x] = g_q[b * ADIM + threadIdx.x];
    __syncthreads();

    float s = 0.f;
    #pragma unroll 8
    for (int a = 0; a < ADIM; a++) s += Wk[(size_t)a * HID + h] * qs[a];
    g_r[b * HID + h] = s * scale;
}

// ---------------------------------------------------------------------------
// Kernel 2: streaming pass over gene_hiddens (819 MB). One warp owns a
// contiguous row range; online-softmax weighted accumulation, 20 regs/lane.
// No intra-block combine (measured: the smem combine cost ~25us on the pass).
// ---------------------------------------------------------------------------
__global__ void __launch_bounds__(256) k_pass1(const float* __restrict__ gh,
                                               int B, int N) {
    int wg   = blockIdx.x * 8 + (threadIdx.x >> 5);
    int b    = wg / WPB;
    int w    = wg % WPB;
    if (b >= B) return;
    int lane = threadIdx.x & 31;

    int rpw = (N + WPB - 1) / WPB;
    int n0  = w * rpw;
    int n1  = min(N, n0 + rpw);

    const float4* rb = reinterpret_cast<const float4*>(g_r + b * HID);
    float4 rr[5], acc[5];
    #pragma unroll
    for (int k = 0; k < 5; k++) {
        rr[k]  = rb[lane + 32 * k];
        acc[k] = make_float4(0.f, 0.f, 0.f, 0.f);
    }

    float m = -1e30f, s = 0.f;
    const float4* base = reinterpret_cast<const float4*>(gh) + (size_t)b * N * (HID / 4);

    for (int n = n0; n < n1; n++) {
        const float4* p = base + (size_t)n * (HID / 4);
        float4 hv[5];
        #pragma unroll
        for (int k = 0; k < 5; k++) hv[k] = __ldcs(p + lane + 32 * k);

        float d = 0.f;
        #pragma unroll
        for (int k = 0; k < 5; k++)
            d += hv[k].x * rr[k].x + hv[k].y * rr[k].y
               + hv[k].z * rr[k].z + hv[k].w * rr[k].w;
        #pragma unroll
        for (int o = 16; o > 0; o >>= 1) d += __shfl_xor_sync(0xffffffffu, d, o);

        if (d > m) {
            float c = __expf(m - d);
            s *= c;
            #pragma unroll
            for (int k = 0; k < 5; k++) {
                acc[k].x *= c; acc[k].y *= c; acc[k].z *= c; acc[k].w *= c;
            }
            m = d;
        }
        float wt = __expf(d - m);
        s += wt;
        #pragma unroll
        for (int k = 0; k < 5; k++) {
            acc[k].x += wt * hv[k].x; acc[k].y += wt * hv[k].y;
            acc[k].z += wt * hv[k].z; acc[k].w += wt * hv[k].w;
        }
    }

    float4* pa = reinterpret_cast<float4*>(g_pacc + (size_t)(b * WPB + w) * HID);
    #pragma unroll
    for (int k = 0; k < 5; k++) pa[lane + 32 * k] = acc[k];
    if (lane == 0) { g_pm[b * WPB + w] = m; g_ps[b * WPB + w] = s; }
}

// ---------------------------------------------------------------------------
// Kernel 3: per-batch softmax-combine scalars: M, wsm[148], invS.
// grid = B, block = 160 (5 warps).
// ---------------------------------------------------------------------------
__global__ void __launch_bounds__(160) k_wsum(int dummy) {
    int b = blockIdx.x;
    int t = threadIdx.x;
    int lane = t & 31, wid = t >> 5;

    __shared__ float sred[8];

    float pm = (t < WPB) ? g_pm[b * WPB + t] : -1e30f;
    float ps = (t < WPB) ? g_ps[b * WPB + t] : 0.f;

    float mv = pm;
    #pragma unroll
    for (int o = 16; o > 0; o >>= 1)
        mv = fmaxf(mv, __shfl_xor_sync(0xffffffffu, mv, o));
    if (lane == 0) sred[wid] = mv;
    __syncthreads();
    float M = fmaxf(fmaxf(sred[0], sred[1]),
                    fmaxf(fmaxf(sred[2], sred[3]), sred[4]));
    __syncthreads();

    float w = (t < WPB) ? __expf(pm - M) : 0.f;
    if (t < WPB) g_wsm[b * WPB + t] = w;

    float sv = w * ps;
    #pragma unroll
    for (int o = 16; o > 0; o >>= 1) sv += __shfl_xor_sync(0xffffffffu, sv, o);
    if (lane == 0) sred[wid] = sv;
    __syncthreads();
    if (t == 0)
        g_invS[b] = 1.f / (sred[0] + sred[1] + sred[2] + sred[3] + sred[4]);
}

// ---------------------------------------------------------------------------
// Kernel 4: pooled[b,h] = invS * sum_i wsm[i] * pacc[b,i,h]
// grid (B, 5) x 256: TWO threads per (b,h), each sums 74 of the 148 partials
// (unrolled -> deep MLP), then pair-combine in shared.
// ---------------------------------------------------------------------------
__global__ void __launch_bounds__(256) k_pooled(int dummy) {
    int b    = blockIdx.x;
    int t    = threadIdx.x;
    int h    = blockIdx.y * 128 + (t & 127);
    int half = t >> 7;

    const float* wsm = g_wsm + b * WPB;
    const float* pa  = g_pacc + (size_t)b * WPB * HID + h;

    float a = 0.f;
    int i0 = half * 74;
    #pragma unroll 8
    for (int i = i0; i < i0 + 74; i++)
        a += __ldg(wsm + i) * pa[(size_t)i * HID];

    __shared__ float red[256];
    red[t] = a;
    __syncthreads();
    if (half == 0)
        g_pooled[b * HID + h] = (a + red[t + 128]) * g_invS[b];
}

// ---------------------------------------------------------------------------
// Kernel 5: y[b,v] = dot(Wv[v,:], pooled[b,:])
// one warp per (b,v) = 10240 warps; v-major so 16 warps share each Wv row.
// ---------------------------------------------------------------------------
__global__ void __launch_bounds__(256) k_y(const float* __restrict__ Wv) {
    int gw   = blockIdx.x * 8 + (threadIdx.x >> 5);   // 0..10239
    int lane = threadIdx.x & 31;
    int v = gw >> 4;
    int b = gw & 15;

    const float* wr = Wv + (size_t)v * HID;
    const float* pr = g_pooled + (size_t)b * HID;
    float s = 0.f;
    #pragma unroll
    for (int k = 0; k < HID / 32; k++) {
        int h = lane + 32 * k;
        s += wr[h] * pr[h];
    }
    #pragma unroll
    for (int o = 16; o > 0; o >>= 1) s += __shfl_xor_sync(0xffffffffu, s, o);
    if (lane == 0) g_y[b * HID + v] = s;
}

// ---------------------------------------------------------------------------
// Kernel 6: LayerNorm over 640. grid=B, block=640.
// ---------------------------------------------------------------------------
__device__ __forceinline__ float block_sum_640(float v, float* sred, int t) {
    int lane = t & 31, wid = t >> 5;            // 20 warps
    #pragma unroll
    for (int o = 16; o > 0; o >>= 1) v += __shfl_xor_sync(0xffffffffu, v, o);
    if (lane == 0) sred[wid] = v;
    __syncthreads();
    if (wid == 0) {
        float x = (lane < 20) ? sred[lane] : 0.f;
        #pragma unroll
        for (int o = 16; o > 0; o >>= 1) x += __shfl_xor_sync(0xffffffffu, x, o);
        if (lane == 0) sred[0] = x;
    }
    __syncthreads();
    float r = sred[0];
    __syncthreads();
    return r;
}

__global__ void __launch_bounds__(640) k_ln(const float* __restrict__ gamma,
                                            const float* __restrict__ beta,
                                            float* __restrict__ out) {
    int b = blockIdx.x;
    int t = threadIdx.x;
    __shared__ float sred[32];

    float x = g_y[b * HID + t];
    float mean = block_sum_640(x, sred, t) * (1.f / HID);
    float dx = x - mean;
    float var = block_sum_640(dx * dx, sred, t) * (1.f / HID);
    out[b * HID + t] = dx * rsqrtf(var + 1e-5f) * gamma[t] + beta[t];
}

// ---------------------------------------------------------------------------
extern "C" void kernel_launch(void* const* d_in, const int* in_sizes, int n_in,
                              void* d_out, int out_size) {
    const float* gh    = (const float*)d_in[0];
    const float* pos   = (const float*)d_in[1];
    const float* Wq    = (const float*)d_in[2];
    const float* Wk    = (const float*)d_in[3];
    const float* Wv    = (const float*)d_in[4];
    const float* gamma = (const float*)d_in[5];
    const float* beta  = (const float*)d_in[6];
    float* out = (float*)d_out;

    int B = in_sizes[1] / HID;             // 16
    int N = in_sizes[0] / (B * HID);       // 20000
    float scale = 1.0f / sqrtf((float)ADIM);

    k_q<<<(B * ADIM) / 8, 256>>>(pos, Wq);            // 256 blocks
    k_r<<<dim3(B, HID / 160), 160>>>(Wk, scale);      // 64 blocks

    int blocks = (B * WPB) / 8;            // 296 blocks = exactly 2/SM
    k_pass1<<<blocks, 256>>>(gh, B, N);

    k_wsum<<<B, 160>>>(0);                            // 16 blocks
    k_pooled<<<dim3(B, HID / 128), 256>>>(0);         // 80 blocks
    k_y<<<(B * HID) / 8, 256>>>(Wv);                  // 1280 blocks
    k_ln<<<B, HID>>>(gamma, beta, out);
}